// round 14
// baseline (speedup 1.0000x reference)
#include <cuda_runtime.h>
#include <cuda_fp16.h>
#include <cstdint>

#define NH    16
#define NK    8
#define D_IN  1024
#define D_H   64
#define MT    128

// scratch (allocation-free rule: __device__ globals)
__device__ float  g_scores[8192 * NK];
__device__ __half g_bf[NH * NK * 64 * 64];   // [h][c][o][i]  (B^T rows, 128B) fp16

__device__ __forceinline__ uint32_t smem_u32(const void* p) {
    uint32_t a;
    asm("{ .reg .u64 t; cvta.to.shared.u64 t, %1; cvt.u32.u64 %0, t; }" : "=r"(a) : "l"(p));
    return a;
}
__device__ __forceinline__ void ldmx4(uint32_t* r, uint32_t a) {
    asm volatile("ldmatrix.sync.aligned.m8n8.x4.shared.b16 {%0,%1,%2,%3}, [%4];"
                 : "=r"(r[0]), "=r"(r[1]), "=r"(r[2]), "=r"(r[3]) : "r"(a));
}
__device__ __forceinline__ void mma16816(float* d, const uint32_t* a, const uint32_t* b) {
    asm volatile("mma.sync.aligned.m16n8k16.row.col.f32.f16.f16.f32 "
                 "{%0,%1,%2,%3}, {%4,%5,%6,%7}, {%8,%9}, {%0,%1,%2,%3};"
                 : "+f"(d[0]), "+f"(d[1]), "+f"(d[2]), "+f"(d[3])
                 : "r"(a[0]), "r"(a[1]), "r"(a[2]), "r"(a[3]), "r"(b[0]), "r"(b[1]));
}

// ---------------------------------------------------------------------------
// Merged prep kernel.
//   blocks [0, 128):       wsplit — B^T fp16, 128B rows: g_bf[((h*8+c)*64+o)*64+i]
//   blocks [128, 128+M/8): scores[m,k] = phi[t,k] + sum_i x[m,i]*diag[k,i]
// ---------------------------------------------------------------------------
__global__ __launch_bounds__(256) void prep_kernel(
        const float* __restrict__ w,
        const float* __restrict__ x, const float* __restrict__ diag,
        const float* __restrict__ phi, int M, int T) {
    __shared__ float sbuf[NK * D_IN];
    int tid = threadIdx.x;

    if (blockIdx.x < NH * NK) {
        int hc = blockIdx.x;
        const float4* wg = (const float4*)(w + (size_t)hc * 4096);
        for (int idx = tid; idx < 1024; idx += 256)
            ((float4*)sbuf)[idx] = wg[idx];
        __syncthreads();

        int o = tid >> 2, q = tid & 3;
        __half hv[16];
#pragma unroll
        for (int j = 0; j < 16; j++)
            hv[j] = __float2half_rn(sbuf[(q * 16 + j) * 64 + o]);   // w[h][c][i][o]
        size_t base = ((size_t)hc * 64 + o) * 64 + q * 16;
        *(uint4*)(g_bf + base)     = ((uint4*)hv)[0];
        *(uint4*)(g_bf + base + 8) = ((uint4*)hv)[1];
        return;
    }

    for (int idx = tid; idx < NK * D_IN / 4; idx += 256)
        ((float4*)sbuf)[idx] = ((const float4*)diag)[idx];
    __syncthreads();

    int warp = tid >> 5, lane = tid & 31;
    int m = (blockIdx.x - NH * NK) * 8 + warp;
    if (m >= M) return;

    const float4* xr = (const float4*)(x + (size_t)m * D_IN);
    float acc[NK];
#pragma unroll
    for (int k = 0; k < NK; k++) acc[k] = 0.f;
#pragma unroll
    for (int j = 0; j < 8; j++) {
        float4 xv = xr[j * 32 + lane];
#pragma unroll
        for (int k = 0; k < NK; k++) {
            float4 dv = *(const float4*)&sbuf[k * D_IN + j * 128 + lane * 4];
            acc[k] += xv.x * dv.x + xv.y * dv.y + xv.z * dv.z + xv.w * dv.w;
        }
    }
#pragma unroll
    for (int k = 0; k < NK; k++)
#pragma unroll
        for (int off = 16; off; off >>= 1)
            acc[k] += __shfl_xor_sync(0xffffffffu, acc[k], off);
    if (lane < NK) {
        float v = 0.f;
#pragma unroll
        for (int k = 0; k < NK; k++)
            if (lane == k) v = acc[k];
        int t = m % T;
        g_scores[m * NK + lane] = phi[t * NK + lane] + v;
    }
}

// ---------------------------------------------------------------------------
// Main: per (128-token tile, head). 256 threads, 8 warps; warp = m16 x n64.
// 2 CTAs/SM (smem 84KB, regs<=124) so one CTA's prologue overlaps the
// other's HMMA stream. Single-pass fp16, score applied in fp32 epilogue.
// smem: B 64K | X 16K | scores 4K = 84 KB.
// ---------------------------------------------------------------------------
#define SB    0
#define SX    65536
#define SS    81920
#define SMEM_TOTAL 86016

__global__ __launch_bounds__(256, 2) void main_kernel(
        const float* __restrict__ x, float* __restrict__ out) {
    extern __shared__ char sm[];
    int tid  = threadIdx.x;
    int lane = tid & 31, wid = tid >> 5;     // wid 0..7
    int h    = blockIdx.y;
    int m0   = blockIdx.x * MT;

    // --- B copy (linear read, swizzled store; 16B granules)
    {
        const uint4* gb = (const uint4*)(g_bf + (size_t)h * NK * 64 * 64);
        for (int i = tid; i < 4096; i += 256) {
            uint32_t byte = i * 16;
            uint32_t dst  = (byte & ~127u) | ((byte & 127u) ^ (((byte >> 7) & 7u) << 4));
            *(uint4*)(sm + SB + dst) = gb[i];
        }
    }
    // --- X fp16 (2 threads per row, 4 float4 groups each)
    {
        int r = tid >> 1, j0 = (tid & 1) * 4;
        const float4* xp = (const float4*)(x + (size_t)(m0 + r) * D_IN + h * D_H);
        uint32_t rsw = (uint32_t)(r & 7) << 4;
#pragma unroll
        for (int jj = 0; jj < 4; jj++) {
            int j = j0 + jj;
            float4 v0 = xp[2 * j], v1 = xp[2 * j + 1];
            float vv[8] = {v0.x, v0.y, v0.z, v0.w, v1.x, v1.y, v1.z, v1.w};
            __half hb[8];
#pragma unroll
            for (int e = 0; e < 8; e++) hb[e] = __float2half_rn(vv[e]);
            uint32_t dst = r * 128 + ((uint32_t)(j * 16) ^ rsw);
            *(uint4*)(sm + SX + dst) = *(uint4*)hb;
        }
    }
    // --- scores tile
    {
        float* ssp = (float*)(sm + SS);
        const float* gs = g_scores + (size_t)m0 * NK;
        for (int i = tid; i < MT * NK; i += 256) ssp[i] = gs[i];
    }
    __syncthreads();

    // --- load X fragments once (m16 per warp)
    int a_r = lane & 15;
    uint32_t a_c = (uint32_t)((lane >> 4) * 16);
    uint32_t xbase = smem_u32(sm);
    uint32_t xh[4][4];
    {
        int row = wid * 16 + a_r;
        uint32_t rsw = (uint32_t)(row & 7) << 4;
#pragma unroll
        for (int ks = 0; ks < 4; ks++) {
            uint32_t off = row * 128 + (((uint32_t)(ks * 32) + a_c) ^ rsw);
            ldmx4(xh[ks], xbase + SX + off);
        }
    }

    // --- B lane address components
    int b_r = (lane & 7) + ((lane >> 4) & 1) * 8;
    uint32_t b_c = (uint32_t)(((lane >> 3) & 1) * 16);
    uint32_t brsw = (uint32_t)(b_r & 7) << 4;
    uint32_t bcol[4];
#pragma unroll
    for (int ks = 0; ks < 4; ks++)
        bcol[ks] = (((uint32_t)(ks * 32) + b_c) ^ brsw);

    float acc[4][2][4];
#pragma unroll
    for (int p = 0; p < 4; p++)
#pragma unroll
        for (int nb = 0; nb < 2; nb++)
#pragma unroll
            for (int e = 0; e < 4; e++) acc[p][nb][e] = 0.f;

    const float* ssp = (const float*)(sm + SS);
    int er0 = wid * 16 + (lane >> 2);

#pragma unroll 1
    for (int c = 0; c < NK; c++) {
        uint32_t bch = xbase + SB + c * 8192;
        float s0 = ssp[er0 * NK + c];
        float s1 = ssp[(er0 + 8) * NK + c];
#pragma unroll
        for (int p = 0; p < 4; p++) {
            float P[2][4];
#pragma unroll
            for (int nb = 0; nb < 2; nb++)
#pragma unroll
                for (int e = 0; e < 4; e++) P[nb][e] = 0.f;

            uint32_t brow = (uint32_t)((p * 16 + b_r) * 128);
#pragma unroll
            for (int ks = 0; ks < 4; ks++) {
                uint32_t bh[4];
                ldmx4(bh, bch + brow + bcol[ks]);
#pragma unroll
                for (int nb = 0; nb < 2; nb++)
                    mma16816(P[nb], xh[ks], bh + 2 * nb);
            }
#pragma unroll
            for (int nb = 0; nb < 2; nb++) {
                acc[p][nb][0] += s0 * P[nb][0];
                acc[p][nb][1] += s0 * P[nb][1];
                acc[p][nb][2] += s1 * P[nb][2];
                acc[p][nb][3] += s1 * P[nb][3];
            }
        }
    }

    // --- store: warp rows [wid*16, wid*16+16)
    {
        int m = m0 + wid * 16 + (lane >> 2);
        float* o0 = out + (size_t)m * D_IN + h * D_H + (lane & 3) * 2;
#pragma unroll
        for (int p = 0; p < 4; p++)
#pragma unroll
            for (int nb = 0; nb < 2; nb++) {
                float2 v0 = make_float2(acc[p][nb][0], acc[p][nb][1]);
                float2 v1 = make_float2(acc[p][nb][2], acc[p][nb][3]);
                *(float2*)(o0 + p * 16 + nb * 8)                     = v0;
                *(float2*)(o0 + p * 16 + nb * 8 + 8 * (size_t)D_IN) = v1;
            }
    }
}

// ---------------------------------------------------------------------------
extern "C" void kernel_launch(void* const* d_in, const int* in_sizes, int n_in,
                              void* d_out, int out_size) {
    const float* x      = (const float*)d_in[0];
    const float* weight = (const float*)d_in[1];
    const float* diag   = (const float*)d_in[2];
    const float* phi    = (const float*)d_in[3];
    float* out          = (float*)d_out;

    int M = in_sizes[0] / D_IN;   // B*T tokens
    int T = in_sizes[3] / NK;     // phi rows

    cudaFuncSetAttribute(main_kernel,
                         cudaFuncAttributeMaxDynamicSharedMemorySize, SMEM_TOTAL);

    prep_kernel<<<NH * NK + (M + 7) / 8, 256>>>(weight, x, diag, phi, M, T);

    dim3 grid(M / MT, NH);
    main_kernel<<<grid, 256, SMEM_TOTAL>>>(x, out);
}

// round 15
// speedup vs baseline: 1.0035x; 1.0035x over previous
#include <cuda_runtime.h>
#include <cuda_fp16.h>
#include <cstdint>

#define NH    16
#define NK    8
#define D_IN  1024
#define D_H   64
#define MT    128

// scratch (allocation-free rule: __device__ globals)
__device__ float  g_scores[8192 * NK];
__device__ __half g_bf[NH * NK * 64 * 64];   // [h][c][o][i]  (B^T rows, 128B) fp16

__device__ __forceinline__ uint32_t smem_u32(const void* p) {
    uint32_t a;
    asm("{ .reg .u64 t; cvta.to.shared.u64 t, %1; cvt.u32.u64 %0, t; }" : "=r"(a) : "l"(p));
    return a;
}
__device__ __forceinline__ void ldmx4(uint32_t* r, uint32_t a) {
    asm volatile("ldmatrix.sync.aligned.m8n8.x4.shared.b16 {%0,%1,%2,%3}, [%4];"
                 : "=r"(r[0]), "=r"(r[1]), "=r"(r[2]), "=r"(r[3]) : "r"(a));
}
__device__ __forceinline__ void mma16816(float* d, const uint32_t* a, const uint32_t* b) {
    asm volatile("mma.sync.aligned.m16n8k16.row.col.f32.f16.f16.f32 "
                 "{%0,%1,%2,%3}, {%4,%5,%6,%7}, {%8,%9}, {%0,%1,%2,%3};"
                 : "+f"(d[0]), "+f"(d[1]), "+f"(d[2]), "+f"(d[3])
                 : "r"(a[0]), "r"(a[1]), "r"(a[2]), "r"(a[3]), "r"(b[0]), "r"(b[1]));
}

// ---------------------------------------------------------------------------
// Merged prep kernel.
//   blocks [0, 128):       wsplit — B^T fp16, 128B rows: g_bf[((h*8+c)*64+o)*64+i]
//   blocks [128, 128+M/8): scores[m,k] = phi[t,k] + sum_i x[m,i]*diag[k,i]
// ---------------------------------------------------------------------------
__global__ __launch_bounds__(256) void prep_kernel(
        const float* __restrict__ w,
        const float* __restrict__ x, const float* __restrict__ diag,
        const float* __restrict__ phi, int M, int T) {
    __shared__ float sbuf[NK * D_IN];
    int tid = threadIdx.x;

    if (blockIdx.x < NH * NK) {
        int hc = blockIdx.x;
        const float4* wg = (const float4*)(w + (size_t)hc * 4096);
        for (int idx = tid; idx < 1024; idx += 256)
            ((float4*)sbuf)[idx] = wg[idx];
        __syncthreads();

        int o = tid >> 2, q = tid & 3;
        __half hv[16];
#pragma unroll
        for (int j = 0; j < 16; j++)
            hv[j] = __float2half_rn(sbuf[(q * 16 + j) * 64 + o]);   // w[h][c][i][o]
        size_t base = ((size_t)hc * 64 + o) * 64 + q * 16;
        *(uint4*)(g_bf + base)     = ((uint4*)hv)[0];
        *(uint4*)(g_bf + base + 8) = ((uint4*)hv)[1];
        return;
    }

    for (int idx = tid; idx < NK * D_IN / 4; idx += 256)
        ((float4*)sbuf)[idx] = ((const float4*)diag)[idx];
    __syncthreads();

    int warp = tid >> 5, lane = tid & 31;
    int m = (blockIdx.x - NH * NK) * 8 + warp;
    if (m >= M) return;

    const float4* xr = (const float4*)(x + (size_t)m * D_IN);
    float acc[NK];
#pragma unroll
    for (int k = 0; k < NK; k++) acc[k] = 0.f;
#pragma unroll
    for (int j = 0; j < 8; j++) {
        float4 xv = xr[j * 32 + lane];
#pragma unroll
        for (int k = 0; k < NK; k++) {
            float4 dv = *(const float4*)&sbuf[k * D_IN + j * 128 + lane * 4];
            acc[k] += xv.x * dv.x + xv.y * dv.y + xv.z * dv.z + xv.w * dv.w;
        }
    }
#pragma unroll
    for (int k = 0; k < NK; k++)
#pragma unroll
        for (int off = 16; off; off >>= 1)
            acc[k] += __shfl_xor_sync(0xffffffffu, acc[k], off);
    if (lane < NK) {
        float v = 0.f;
#pragma unroll
        for (int k = 0; k < NK; k++)
            if (lane == k) v = acc[k];
        int t = m % T;
        g_scores[m * NK + lane] = phi[t * NK + lane] + v;
    }
}

// ---------------------------------------------------------------------------
// Main: per (128-token tile, head). 256 threads, 8 warps; warp = m16 x n64.
// 2 CTAs/SM (smem 84KB, regs<=124) so one CTA's prologue overlaps the
// other's HMMA stream. Single-pass fp16, score applied in fp32 epilogue.
// smem: B 64K | X 16K | scores 4K = 84 KB.
// ---------------------------------------------------------------------------
#define SB    0
#define SX    65536
#define SS    81920
#define SMEM_TOTAL 86016

__global__ __launch_bounds__(256, 2) void main_kernel(
        const float* __restrict__ x, float* __restrict__ out) {
    extern __shared__ char sm[];
    int tid  = threadIdx.x;
    int lane = tid & 31, wid = tid >> 5;     // wid 0..7
    int h    = blockIdx.y;
    int m0   = blockIdx.x * MT;

    // --- B copy (linear read, swizzled store; 16B granules)
    {
        const uint4* gb = (const uint4*)(g_bf + (size_t)h * NK * 64 * 64);
        for (int i = tid; i < 4096; i += 256) {
            uint32_t byte = i * 16;
            uint32_t dst  = (byte & ~127u) | ((byte & 127u) ^ (((byte >> 7) & 7u) << 4));
            *(uint4*)(sm + SB + dst) = gb[i];
        }
    }
    // --- X fp16 (2 threads per row, 4 float4 groups each)
    {
        int r = tid >> 1, j0 = (tid & 1) * 4;
        const float4* xp = (const float4*)(x + (size_t)(m0 + r) * D_IN + h * D_H);
        uint32_t rsw = (uint32_t)(r & 7) << 4;
#pragma unroll
        for (int jj = 0; jj < 4; jj++) {
            int j = j0 + jj;
            float4 v0 = xp[2 * j], v1 = xp[2 * j + 1];
            float vv[8] = {v0.x, v0.y, v0.z, v0.w, v1.x, v1.y, v1.z, v1.w};
            __half hb[8];
#pragma unroll
            for (int e = 0; e < 8; e++) hb[e] = __float2half_rn(vv[e]);
            uint32_t dst = r * 128 + ((uint32_t)(j * 16) ^ rsw);
            *(uint4*)(sm + SX + dst) = *(uint4*)hb;
        }
    }
    // --- scores tile
    {
        float* ssp = (float*)(sm + SS);
        const float* gs = g_scores + (size_t)m0 * NK;
        for (int i = tid; i < MT * NK; i += 256) ssp[i] = gs[i];
    }
    __syncthreads();

    // --- load X fragments once (m16 per warp)
    int a_r = lane & 15;
    uint32_t a_c = (uint32_t)((lane >> 4) * 16);
    uint32_t xbase = smem_u32(sm);
    uint32_t xh[4][4];
    {
        int row = wid * 16 + a_r;
        uint32_t rsw = (uint32_t)(row & 7) << 4;
#pragma unroll
        for (int ks = 0; ks < 4; ks++) {
            uint32_t off = row * 128 + (((uint32_t)(ks * 32) + a_c) ^ rsw);
            ldmx4(xh[ks], xbase + SX + off);
        }
    }

    // --- B lane address components
    int b_r = (lane & 7) + ((lane >> 4) & 1) * 8;
    uint32_t b_c = (uint32_t)(((lane >> 3) & 1) * 16);
    uint32_t brsw = (uint32_t)(b_r & 7) << 4;
    uint32_t bcol[4];
#pragma unroll
    for (int ks = 0; ks < 4; ks++)
        bcol[ks] = (((uint32_t)(ks * 32) + b_c) ^ brsw);

    float acc[4][2][4];
#pragma unroll
    for (int p = 0; p < 4; p++)
#pragma unroll
        for (int nb = 0; nb < 2; nb++)
#pragma unroll
            for (int e = 0; e < 4; e++) acc[p][nb][e] = 0.f;

    const float* ssp = (const float*)(sm + SS);
    int er0 = wid * 16 + (lane >> 2);

#pragma unroll 1
    for (int c = 0; c < NK; c++) {
        uint32_t bch = xbase + SB + c * 8192;
        float s0 = ssp[er0 * NK + c];
        float s1 = ssp[(er0 + 8) * NK + c];
#pragma unroll
        for (int p = 0; p < 4; p++) {
            float P[2][4];
#pragma unroll
            for (int nb = 0; nb < 2; nb++)
#pragma unroll
                for (int e = 0; e < 4; e++) P[nb][e] = 0.f;

            uint32_t brow = (uint32_t)((p * 16 + b_r) * 128);
#pragma unroll
            for (int ks = 0; ks < 4; ks++) {
                uint32_t bh[4];
                ldmx4(bh, bch + brow + bcol[ks]);
#pragma unroll
                for (int nb = 0; nb < 2; nb++)
                    mma16816(P[nb], xh[ks], bh + 2 * nb);
            }
#pragma unroll
            for (int nb = 0; nb < 2; nb++) {
                acc[p][nb][0] += s0 * P[nb][0];
                acc[p][nb][1] += s0 * P[nb][1];
                acc[p][nb][2] += s1 * P[nb][2];
                acc[p][nb][3] += s1 * P[nb][3];
            }
        }
    }

    // --- store: warp rows [wid*16, wid*16+16)
    {
        int m = m0 + wid * 16 + (lane >> 2);
        float* o0 = out + (size_t)m * D_IN + h * D_H + (lane & 3) * 2;
#pragma unroll
        for (int p = 0; p < 4; p++)
#pragma unroll
            for (int nb = 0; nb < 2; nb++) {
                float2 v0 = make_float2(acc[p][nb][0], acc[p][nb][1]);
                float2 v1 = make_float2(acc[p][nb][2], acc[p][nb][3]);
                *(float2*)(o0 + p * 16 + nb * 8)                     = v0;
                *(float2*)(o0 + p * 16 + nb * 8 + 8 * (size_t)D_IN) = v1;
            }
    }
}

// ---------------------------------------------------------------------------
extern "C" void kernel_launch(void* const* d_in, const int* in_sizes, int n_in,
                              void* d_out, int out_size) {
    const float* x      = (const float*)d_in[0];
    const float* weight = (const float*)d_in[1];
    const float* diag   = (const float*)d_in[2];
    const float* phi    = (const float*)d_in[3];
    float* out          = (float*)d_out;

    int M = in_sizes[0] / D_IN;   // B*T tokens
    int T = in_sizes[3] / NK;     // phi rows

    cudaFuncSetAttribute(main_kernel,
                         cudaFuncAttributeMaxDynamicSharedMemorySize, SMEM_TOTAL);

    prep_kernel<<<NH * NK + (M + 7) / 8, 256>>>(weight, x, diag, phi, M, T);

    dim3 grid(M / MT, NH);
    main_kernel<<<grid, 256, SMEM_TOTAL>>>(x, out);
}